// round 5
// baseline (speedup 1.0000x reference)
#include <cuda_runtime.h>
#include <cuda_bf16.h>

// VTMUpsampler, scale_factor=3, x:(2,8,540,960) f32 -> out:(2,8,1620,2880) f32
//
// Degenerate-structure exploit (exact replication of the reference math):
//   ref = int(i*16384/3); integer = ref>>4 (= ~341.33*i); frac cycles {0,5,10}.
//   Horizontal: j=0 -> 0.25*x[...,0]; j=1 -> phase5 dot over cols 338..345;
//               j=2 -> phase10 dot over cols 679..686; j>=3 -> all taps clamp
//               to col 959, filter rows sum to 64/256=0.25 -> 0.25*x[...,959].
//   Vertical  : i=0 -> 0.25*Hrow(0); i=1 -> phase5 dot over Hrows 338..345;
//               i>=2 -> all taps clamp to row 539 -> 0.25*Hrow(539).
//   Final /4096 folded into the 4 scalars per output row.
//
// R4: one row per block (grid 25920, perfectly wave-balanced). EVERY thread
// computes the row's 4 params redundantly (uniform addresses -> warp-broadcast
// loads; L1-resident after the first block per SM), so there is no barrier and
// no thread-0 funnel — each warp starts its plain float4 stores as soon as its
// own (mostly L1-hit) loads return. No __stcs (regressed DRAM% in R2).

#define BB 2
#define CC 8
#define HH 540
#define WW 960
#define OH 1620
#define OW 2880
#define NBC (BB * CC)
#define NROWS (NBC * OH)
#define OW4 (OW / 4)

__device__ __forceinline__ void hrow(const float* __restrict__ row,
                                     const float* __restrict__ c5,
                                     const float* __restrict__ c10,
                                     float q, float out4[4]) {
    out4[0] = q * row[0];
    float a = 0.f, b = 0.f;
#pragma unroll
    for (int k = 0; k < 8; k++) {
        a += c5[k]  * row[338 + k];
        b += c10[k] * row[679 + k];
    }
    out4[1] = a;
    out4[2] = b;
    out4[3] = q * row[WW - 1];
}

__global__ void __launch_bounds__(256) fused_kernel(const float* __restrict__ x,
                                                    const float* __restrict__ filt,
                                                    float* __restrict__ out) {
    const int row = blockIdx.x;            // 0 .. NROWS-1
    const int bc  = row / OH;
    const int i   = row - bc * OH;

    // Per-thread (uniform) param computation — broadcast loads, no barrier.
    float c5[8], c10[8];
#pragma unroll
    for (int k = 0; k < 8; k++) {
        c5[k]  = filt[5 * 8 + k];
        c10[k] = filt[10 * 8 + k];
    }
    const float q   = filt[0 * 8 + 3];     // 64/256 = 0.25 (= every row's sum)
    const float inv = 1.0f / 4096.0f;
    const float* xp = x + (size_t)bc * HH * WW;

    float t[4], p[4];
    if (i >= 2) {                          // 25888 of 25920 blocks
        hrow(xp + (size_t)(HH - 1) * WW, c5, c10, q, t);
#pragma unroll
        for (int j = 0; j < 4; j++) p[j] = q * t[j] * inv;
    } else if (i == 0) {
        hrow(xp, c5, c10, q, t);
#pragma unroll
        for (int j = 0; j < 4; j++) p[j] = q * t[j] * inv;
    } else {                               // i == 1
        float acc[4] = {0.f, 0.f, 0.f, 0.f};
#pragma unroll
        for (int k = 0; k < 8; k++) {
            hrow(xp + (size_t)(338 + k) * WW, c5, c10, q, t);
#pragma unroll
            for (int j = 0; j < 4; j++) acc[j] += c5[k] * t[j];
        }
#pragma unroll
        for (int j = 0; j < 4; j++) p[j] = acc[j] * inv;
    }

    const float4 pv = make_float4(p[0], p[1], p[2], p[3]);
    const float4 tv = make_float4(p[3], p[3], p[3], p[3]);
    float4* __restrict__ orow = (float4*)(out + (size_t)row * OW);

    for (int c4 = threadIdx.x; c4 < OW4; c4 += 256) {
        orow[c4] = (c4 == 0) ? pv : tv;
    }
}

extern "C" void kernel_launch(void* const* d_in, const int* in_sizes, int n_in,
                              void* d_out, int out_size) {
    const float* x    = (const float*)d_in[0];
    const float* filt = (const float*)d_in[1];
    float* out        = (float*)d_out;

    fused_kernel<<<NROWS, 256>>>(x, filt, out);
}

// round 6
// speedup vs baseline: 1.3770x; 1.3770x over previous
#include <cuda_runtime.h>
#include <cuda_bf16.h>

// VTMUpsampler, scale_factor=3, x:(2,8,540,960) f32 -> out:(2,8,1620,2880) f32
//
// Degenerate-structure exploit (exact replication of the reference math):
//   ref = int(i*16384/3); integer = ref>>4 (= ~341.33*i); frac cycles {0,5,10}.
//   Horizontal: j=0 -> 0.25*x[...,0]; j=1 -> phase5 dot over cols 338..345;
//               j=2 -> phase10 dot over cols 679..686; j>=3 -> all taps clamp
//               to col 959, filter rows sum to 64/256=0.25 -> 0.25*x[...,959].
//   Vertical  : i=0 -> 0.25*Hrow(0); i=1 -> phase5 dot over Hrows 338..345;
//               i>=2 -> all taps clamp to row 539 -> 0.25*Hrow(539).
//   Final /4096 folded into the 4 scalars per output-row class.
//
// R5: two kernels again (R1 structure was right; its prep was just serial).
//  - prep: 16 blocks x 10 warps; warp w computes one Hrow with lane-parallel
//    taps + fixed-order shfl tree reduce (deterministic). All ~180 loads per
//    channel issue in one memory round -> prep ~1-2us (was ~14-17us in R1).
//  - fill: one row per block (25920, wave-balanced), prologue is ONE uniform
//    LDG.128 of the row's float4 param; 3 front-batched float4 stores/thread.

#define BB 2
#define CC 8
#define HH 540
#define WW 960
#define OH 1620
#define OW 2880
#define NBC (BB * CC)
#define OW4 (OW / 4)          /* 720 */

__device__ float4 g_param4[NBC][3];   // [bc][cls] = {col0, col1, col2, tail}

// ---------------- prep ----------------
// warp 0 -> Hrow(0) (class 0), warp 1 -> Hrow(539) (class 2),
// warps 2..9 -> Hrow(338+w-2) (inputs of class 1 vertical dot).
__global__ void __launch_bounds__(320) prep_kernel(const float* __restrict__ x,
                                                   const float* __restrict__ filt) {
    __shared__ float4 s_t[10];

    const int bc   = blockIdx.x;
    const int warp = threadIdx.x >> 5;
    const int lane = threadIdx.x & 31;

    const float q   = filt[0 * 8 + 3];      // 64/256 = 0.25 (= every row's sum)
    const float inv = 1.0f / 4096.0f;

    int rowidx = (warp == 0) ? 0 : (warp == 1) ? (HH - 1) : (338 + warp - 2);
    const float* row = x + (size_t)bc * HH * WW + (size_t)rowidx * WW;

    // lanes 0..7: phase-5 taps; lanes 8..15: phase-10 taps; 16/17: edge cols
    float part = 0.f, e = 0.f;
    if (lane < 8)        part = filt[5 * 8 + lane]        * row[338 + lane];
    else if (lane < 16)  part = filt[10 * 8 + (lane - 8)] * row[679 + (lane - 8)];
    else if (lane == 16) e = row[0];
    else if (lane == 17) e = row[WW - 1];

    // fixed-order tree reduce within each aligned 8-lane group
    part += __shfl_xor_sync(0xffffffffu, part, 4);
    part += __shfl_xor_sync(0xffffffffu, part, 2);
    part += __shfl_xor_sync(0xffffffffu, part, 1);

    float t1 = __shfl_sync(0xffffffffu, part, 0);
    float t2 = __shfl_sync(0xffffffffu, part, 8);
    float t0 = q * __shfl_sync(0xffffffffu, e, 16);
    float t3 = q * __shfl_sync(0xffffffffu, e, 17);

    if (lane == 0) s_t[warp] = make_float4(t0, t1, t2, t3);
    __syncthreads();

    if (threadIdx.x == 0) {
        float4 a = s_t[0];                   // Hrow(0)
        g_param4[bc][0] = make_float4(q * a.x * inv, q * a.y * inv,
                                      q * a.z * inv, q * a.w * inv);
        float4 b = s_t[1];                   // Hrow(539)
        g_param4[bc][2] = make_float4(q * b.x * inv, q * b.y * inv,
                                      q * b.z * inv, q * b.w * inv);
        float acc0 = 0.f, acc1 = 0.f, acc2 = 0.f, acc3 = 0.f;
#pragma unroll
        for (int k = 0; k < 8; k++) {
            float c = filt[5 * 8 + k];
            float4 t = s_t[2 + k];
            acc0 += c * t.x; acc1 += c * t.y; acc2 += c * t.z; acc3 += c * t.w;
        }
        g_param4[bc][1] = make_float4(acc0 * inv, acc1 * inv,
                                      acc2 * inv, acc3 * inv);
    }
}

// ---------------- fill ----------------
__global__ void __launch_bounds__(256) fill_kernel(float* __restrict__ out) {
    const int i  = blockIdx.x;      // row within channel, 0..1619
    const int bc = blockIdx.y;      // 0..15
    const int cls = (i < 2) ? i : 2;

    const float4 p  = g_param4[bc][cls];          // one uniform LDG.128
    const float4 tv = make_float4(p.w, p.w, p.w, p.w);

    float4* __restrict__ orow = (float4*)(out + ((size_t)bc * OH + i) * OW);
    const int tid = threadIdx.x;

    // 720 = 256 + 256 + 208 : front-batched stores, no loop
    orow[tid]       = (tid == 0) ? p : tv;
    orow[tid + 256] = tv;
    if (tid < OW4 - 512)
        orow[tid + 512] = tv;
}

extern "C" void kernel_launch(void* const* d_in, const int* in_sizes, int n_in,
                              void* d_out, int out_size) {
    const float* x    = (const float*)d_in[0];
    const float* filt = (const float*)d_in[1];
    float* out        = (float*)d_out;

    prep_kernel<<<NBC, 320>>>(x, filt);
    fill_kernel<<<dim3(OH, NBC), 256>>>(out);
}

// round 7
// speedup vs baseline: 1.3882x; 1.0081x over previous
#include <cuda_runtime.h>
#include <cuda_bf16.h>

// VTMUpsampler, scale_factor=3, x:(2,8,540,960) f32 -> out:(2,8,1620,2880) f32
//
// Degenerate-structure exploit (exact replication of the reference math):
//   ref = int(i*16384/3); integer = ref>>4 (= ~341.33*i); frac cycles {0,5,10}.
//   Horizontal: j=0 -> 0.25*x[...,0]; j=1 -> phase5 dot over cols 338..345;
//               j=2 -> phase10 dot over cols 679..686; j>=3 -> all taps clamp
//               to col 959, filter rows sum to 64/256=0.25 -> 0.25*x[...,959].
//   Vertical  : i=0 -> 0.25*Hrow(0); i=1 -> phase5 dot over Hrows 338..345;
//               i>=2 -> all taps clamp to row 539 -> 0.25*Hrow(539).
//   Final /4096 folded into the 4 scalars per output-row class.
//
// R6 = R5 + PDL: fill is launched with programmatic stream serialization so its
// blocks start while prep drains; they stall at griddepcontrol.wait only until
// prep's blocks execute griddepcontrol.launch_dependents (issued right after
// the param stores are visible). Kills the ~4-5us prep->fill serialization.

#define BB 2
#define CC 8
#define HH 540
#define WW 960
#define OH 1620
#define OW 2880
#define NBC (BB * CC)
#define OW4 (OW / 4)          /* 720 */

__device__ float4 g_param4[NBC][3];   // [bc][cls] = {col0, col1, col2, tail}

// ---------------- prep ----------------
// warp 0 -> Hrow(0) (class 0), warp 1 -> Hrow(539) (class 2),
// warps 2..9 -> Hrow(338+w-2) (inputs of class 1 vertical dot).
__global__ void __launch_bounds__(320) prep_kernel(const float* __restrict__ x,
                                                   const float* __restrict__ filt) {
    __shared__ float4 s_t[10];

    const int bc   = blockIdx.x;
    const int warp = threadIdx.x >> 5;
    const int lane = threadIdx.x & 31;

    const float q   = filt[0 * 8 + 3];      // 64/256 = 0.25 (= every row's sum)
    const float inv = 1.0f / 4096.0f;

    int rowidx = (warp == 0) ? 0 : (warp == 1) ? (HH - 1) : (338 + warp - 2);
    const float* row = x + (size_t)bc * HH * WW + (size_t)rowidx * WW;

    // lanes 0..7: phase-5 taps; lanes 8..15: phase-10 taps; 16/17: edge cols
    float part = 0.f, e = 0.f;
    if (lane < 8)        part = filt[5 * 8 + lane]        * row[338 + lane];
    else if (lane < 16)  part = filt[10 * 8 + (lane - 8)] * row[679 + (lane - 8)];
    else if (lane == 16) e = row[0];
    else if (lane == 17) e = row[WW - 1];

    // fixed-order tree reduce within each aligned 8-lane group
    part += __shfl_xor_sync(0xffffffffu, part, 4);
    part += __shfl_xor_sync(0xffffffffu, part, 2);
    part += __shfl_xor_sync(0xffffffffu, part, 1);

    float t1 = __shfl_sync(0xffffffffu, part, 0);
    float t2 = __shfl_sync(0xffffffffu, part, 8);
    float t0 = q * __shfl_sync(0xffffffffu, e, 16);
    float t3 = q * __shfl_sync(0xffffffffu, e, 17);

    if (lane == 0) s_t[warp] = make_float4(t0, t1, t2, t3);
    __syncthreads();

    if (threadIdx.x == 0) {
        float4 a = s_t[0];                   // Hrow(0)
        g_param4[bc][0] = make_float4(q * a.x * inv, q * a.y * inv,
                                      q * a.z * inv, q * a.w * inv);
        float4 b = s_t[1];                   // Hrow(539)
        g_param4[bc][2] = make_float4(q * b.x * inv, q * b.y * inv,
                                      q * b.z * inv, q * b.w * inv);
        float acc0 = 0.f, acc1 = 0.f, acc2 = 0.f, acc3 = 0.f;
#pragma unroll
        for (int k = 0; k < 8; k++) {
            float c = filt[5 * 8 + k];
            float4 t = s_t[2 + k];
            acc0 += c * t.x; acc1 += c * t.y; acc2 += c * t.z; acc3 += c * t.w;
        }
        g_param4[bc][1] = make_float4(acc0 * inv, acc1 * inv,
                                      acc2 * inv, acc3 * inv);
    }
    __syncthreads();                         // param stores visible block-wide
    // release dependent (fill) grid; prior writes visible past its wait
    asm volatile("griddepcontrol.launch_dependents;" ::: "memory");
}

// ---------------- fill ----------------
__global__ void __launch_bounds__(256) fill_kernel(float* __restrict__ out) {
    const int i  = blockIdx.x;      // row within channel, 0..1619
    const int bc = blockIdx.y;      // 0..15
    const int cls = (i < 2) ? i : 2;
    const int tid = threadIdx.x;

    float4* __restrict__ orow = (float4*)(out + ((size_t)bc * OH + i) * OW);

    // block here (prologue above already done) until prep's params are ready
    asm volatile("griddepcontrol.wait;" ::: "memory");

    const float4 p  = g_param4[bc][cls];          // one uniform LDG.128
    const float4 tv = make_float4(p.w, p.w, p.w, p.w);

    // 720 = 256 + 256 + 208 : front-batched stores, no loop
    orow[tid]       = (tid == 0) ? p : tv;
    orow[tid + 256] = tv;
    if (tid < OW4 - 512)
        orow[tid + 512] = tv;
}

extern "C" void kernel_launch(void* const* d_in, const int* in_sizes, int n_in,
                              void* d_out, int out_size) {
    const float* x    = (const float*)d_in[0];
    const float* filt = (const float*)d_in[1];
    float* out        = (float*)d_out;

    prep_kernel<<<NBC, 320>>>(x, filt);

    cudaLaunchConfig_t cfg = {};
    cfg.gridDim  = dim3(OH, NBC);
    cfg.blockDim = dim3(256);
    cfg.stream   = 0;
    cudaLaunchAttribute attr[1];
    attr[0].id = cudaLaunchAttributeProgrammaticStreamSerialization;
    attr[0].val.programmaticStreamSerializationAllowed = 1;
    cfg.attrs    = attr;
    cfg.numAttrs = 1;
    cudaLaunchKernelEx(&cfg, fill_kernel, out);
}